// round 13
// baseline (speedup 1.0000x reference)
#include <cuda_runtime.h>

#define NUM_BINS  512
#define NUM_NODES 128
#define N_PAIRS   1024
#define K_ELEMS   16384
#define NREP      16            // hist replicas: 32KB/CTA -> 4 CTAs/SM
#define LREP      8             // lookup: 8 float2 replicas -> 32KB, 4 CTAs/SM

#define TASKS_PER_PAIR 8
#define CHUNK_F4   512          // float4 per task (2048 elems)
#define TOTAL_TASKS (N_PAIRS * TASKS_PER_PAIR)   // 8192
#define HIST_BLOCKS   592       // 148 SMs * 4 CTAs (32KB smem) = one full wave
#define LOOKUP_BLOCKS 592       // 148 SMs * 4 CTAs (32KB smem) = one full wave

// Scratch (allocation-free rule: __device__ globals, zero-initialized at load)
__device__ float g_hist[NUM_NODES * NUM_BINS];
__device__ float g_cdf[NUM_NODES * NUM_BINS];
// 2-byte lookup code per element: bin index if valid, 0xFFFF sentinel if not.
__device__ unsigned short g_code[(size_t)N_PAIRS * K_ELEMS];

extern __shared__ float sh_dyn[];   // role depends on kernel

// ---------------------------------------------------------------------------
// Kernel 1: persistent hist, 4 CTAs/SM (32-reg cap, 32KB smem).
// 16-way replicated smem histogram, conflict-free replica index
// rep = (lane&15 + 8*(lane>>4)) & 15. Total weight is recovered as the scan
// total in cdf_kernel (all residuals in-range), so no wsum machinery.
// Histogram atomic is unconditional with a 1-op clamp. Zeroing fused into
// the reduction. g_hist zero on entry. (Unchanged from R12 — near floor.)
// ---------------------------------------------------------------------------
__global__ void __launch_bounds__(512, 4) hist_kernel(
    const float* __restrict__ res, const float* __restrict__ wgt,
    const int* __restrict__ src, const int* __restrict__ dst)
{
    float* tab = sh_dyn;              // NUM_BINS * NREP floats = 32 KB

    const int tid  = threadIdx.x;
    const int lane = tid & 31;
    const int rep  = (lane + ((lane >> 4) << 3)) & 15;   // conflict-free replica

    // one-time zero of the replicated histogram
    float4* shz = (float4*)tab;
    #pragma unroll
    for (int i = 0; i < (NUM_BINS * NREP / 4) / 512; i++)
        shz[tid + i * 512] = make_float4(0.f, 0.f, 0.f, 0.f);
    __syncthreads();

    int lo = (int)(((long long)blockIdx.x       * TOTAL_TASKS) / HIST_BLOCKS);
    int hi = (int)(((long long)(blockIdx.x + 1) * TOTAL_TASKS) / HIST_BLOCKS);

    int t = lo;
    while (t < hi) {
        const int p    = t / TASKS_PER_PAIR;
        const int tend = min(hi, (p + 1) * TASKS_PER_PAIR);

        const float4* r4 = (const float4*)(res + (size_t)p * K_ELEMS);
        const float4* w4 = (const float4*)(wgt + (size_t)p * K_ELEMS);
        ushort4* c4 = (ushort4*)(g_code + (size_t)p * K_ELEMS);

        const int i0 = (t    - p * TASKS_PER_PAIR) * CHUNK_F4;
        const int i1 = (tend - p * TASKS_PER_PAIR) * CHUNK_F4;

        for (int i = i0 + tid; i < i1; i += 512) {
            float4 rv = __ldcs(&r4[i]);   // read-once: stream past L2
            float4 wv = __ldcs(&w4[i]);
            float rr[4] = {rv.x, rv.y, rv.z, rv.w};
            float ww[4] = {wv.x, wv.y, wv.z, wv.w};
            unsigned short cc[4];
            #pragma unroll
            for (int j = 0; j < 4; j++) {
                float x = rr[j] * 512.0f;             // *2^9 exact in fp32
                int b  = min(__float2int_rd(x), NUM_BINS - 1);  // r in [0,1)
                atomicAdd(&tab[b * NREP + rep], ww[j]);         // conflict-free
                int b2 = __float2int_rd(x + 0.5f);    // lookup bin
                bool valid = ((unsigned)b2 < NUM_BINS) && (ww[j] > 0.0f);
                cc[j] = valid ? (unsigned short)b2 : (unsigned short)0xFFFFu;
            }
            c4[i] = make_ushort4(cc[0], cc[1], cc[2], cc[3]);
        }
        __syncthreads();   // all atomics for this pair done

        // ---- reduce 16 replicas -> 1 per bin, zero slots behind the read.
        const int bin = tid;   // 512 threads == 512 bins
        float h = 0.0f;
        #pragma unroll
        for (int step = 0; step < NREP; step++) {
            int r = ((lane >> 1) + step) & (NREP - 1);
            h += tab[bin * NREP + r];
            tab[bin * NREP + r] = 0.0f;            // ready for next segment
        }

        const int s = src[p];
        const int d = dst[p];
        atomicAdd(&g_hist[s * NUM_BINS + bin], h);
        atomicAdd(&g_hist[d * NUM_BINS + bin], h);
        __syncthreads();           // next segment's atomics start after this

        t = tend;
    }
}

// ---------------------------------------------------------------------------
// Kernel 2: cdf[node,:] = cumsum(hist[node,:]) / (total + 1e-10); the grand
// total of the scan equals tw[node]. Resets g_hist for the next invocation.
// ---------------------------------------------------------------------------
__global__ __launch_bounds__(512) void cdf_kernel() {
    __shared__ float warp_sums[16];
    __shared__ float inv_total;

    const int node = blockIdx.x;
    const int tid  = threadIdx.x;

    float h = g_hist[node * NUM_BINS + tid];
    g_hist[node * NUM_BINS + tid] = 0.0f;     // reset for next call
    float x = h;

    #pragma unroll
    for (int o = 1; o < 32; o <<= 1) {
        float y = __shfl_up_sync(0xffffffffu, x, o);
        if ((tid & 31) >= o) x += y;
    }
    if ((tid & 31) == 31) warp_sums[tid >> 5] = x;
    __syncthreads();

    if (tid < 16) {
        float s = warp_sums[tid];
        #pragma unroll
        for (int o = 1; o < 16; o <<= 1) {
            float y = __shfl_up_sync(0x0000ffffu, s, o);
            if (tid >= o) s += y;
        }
        warp_sums[tid] = s;
        if (tid == 15) inv_total = 1.0f / (s + 1e-10f);   // grand total == tw
    }
    __syncthreads();

    float base = (tid >= 32) ? warp_sums[(tid >> 5) - 1] : 0.0f;
    g_cdf[node * NUM_BINS + tid] = (x + base) * inv_total;
}

// ---------------------------------------------------------------------------
// Kernel 3: persistent lookup, 4 CTAs/SM. STORE-PATH EXPERIMENT:
// default (evict-normal) stores instead of __stcs, and 2 code vectors in
// flight per iteration for deeper store-issue ILP.
// Output layout: out[0 : N*K) = src_cdf, out[N*K : 2*N*K) = dst_cdf.
// ---------------------------------------------------------------------------
__device__ __forceinline__ void lk_one(
    ushort4 cv, const float2* tab, int laneL, float4& os, float4& od)
{
    unsigned short cc[4] = {cv.x, cv.y, cv.z, cv.w};
    float* pos = (float*)&os;
    float* pod = (float*)&od;
    #pragma unroll
    for (int j = 0; j < 4; j++) {
        unsigned short c = cc[j];
        if (c < NUM_BINS) {
            float2 v = tab[(int)c * LREP + laneL];
            pos[j] = v.x;
            pod[j] = v.y;
        } else {
            pos[j] = 2.0f;
            pod[j] = 2.0f;
        }
    }
}

__global__ void __launch_bounds__(512, 4) lookup_kernel(
    const int* __restrict__ src, const int* __restrict__ dst,
    float* __restrict__ out)
{
    float2* tab = (float2*)sh_dyn;    // NUM_BINS * LREP float2 = 32 KB

    const int tid   = threadIdx.x;
    const int laneL = tid & (LREP - 1);

    int lo = (int)(((long long)blockIdx.x       * TOTAL_TASKS) / LOOKUP_BLOCKS);
    int hi = (int)(((long long)(blockIdx.x + 1) * TOTAL_TASKS) / LOOKUP_BLOCKS);

    int t = lo;
    while (t < hi) {
        const int p    = t / TASKS_PER_PAIR;
        const int tend = min(hi, (p + 1) * TASKS_PER_PAIR);

        __syncthreads();   // previous segment's smem readers are done
        const int s = src[p];
        const int d = dst[p];
        {
            float2 v = make_float2(g_cdf[s * NUM_BINS + tid],
                                   g_cdf[d * NUM_BINS + tid]);
            #pragma unroll
            for (int r = 0; r < LREP; r++)          // stagger: conflict-free STS
                tab[tid * LREP + ((r + tid) & (LREP - 1))] = v;
        }
        __syncthreads();

        const ushort4* c4 = (const ushort4*)(g_code + (size_t)p * K_ELEMS);
        float4* o_s = (float4*)(out + (size_t)p * K_ELEMS);
        float4* o_d = (float4*)(out + (size_t)(N_PAIRS + p) * K_ELEMS);

        const int i0 = (t    - p * TASKS_PER_PAIR) * CHUNK_F4;
        const int i1 = (tend - p * TASKS_PER_PAIR) * CHUNK_F4;

        // two code vectors in flight per iteration (stride 1024)
        int i = i0 + tid;
        for (; i + 512 < i1; i += 1024) {
            ushort4 cv0 = c4[i];
            ushort4 cv1 = c4[i + 512];
            float4 os0, od0, os1, od1;
            lk_one(cv0, tab, laneL, os0, od0);
            lk_one(cv1, tab, laneL, os1, od1);
            o_s[i]       = os0;
            o_d[i]       = od0;
            o_s[i + 512] = os1;
            o_d[i + 512] = od1;
        }
        if (i < i1) {
            ushort4 cv = c4[i];
            float4 os, od;
            lk_one(cv, tab, laneL, os, od);
            o_s[i] = os;
            o_d[i] = od;
        }

        t = tend;
    }
}

// ---------------------------------------------------------------------------
extern "C" void kernel_launch(void* const* d_in, const int* in_sizes, int n_in,
                              void* d_out, int out_size)
{
    const float* res = (const float*)d_in[0];
    const float* wgt = (const float*)d_in[1];
    const int*   src = (const int*)d_in[2];
    const int*   dst = (const int*)d_in[3];
    float*       out = (float*)d_out;

    const int smem_h = NUM_BINS * NREP * sizeof(float);    // 32 KB
    const int smem_l = NUM_BINS * LREP * sizeof(float2);   // 32 KB
    cudaFuncSetAttribute(hist_kernel,
                         cudaFuncAttributeMaxDynamicSharedMemorySize, smem_h);
    cudaFuncSetAttribute(lookup_kernel,
                         cudaFuncAttributeMaxDynamicSharedMemorySize, smem_l);

    hist_kernel<<<HIST_BLOCKS, 512, smem_h>>>(res, wgt, src, dst);
    cdf_kernel<<<NUM_NODES, 512>>>();
    lookup_kernel<<<LOOKUP_BLOCKS, 512, smem_l>>>(src, dst, out);
}

// round 14
// speedup vs baseline: 1.0907x; 1.0907x over previous
#include <cuda_runtime.h>

#define NUM_BINS  512
#define NUM_NODES 128
#define N_PAIRS   1024
#define K_ELEMS   16384
#define NREP      16            // hist replicas: 32KB/CTA -> 4 CTAs/SM
#define LREP      16            // lookup: 16 float2 replicas -> conflict-free LDS.64

#define TASKS_PER_PAIR 8
#define CHUNK_F4   512          // float4 per task (2048 elems)
#define TOTAL_TASKS (N_PAIRS * TASKS_PER_PAIR)   // 8192
#define HIST_BLOCKS   592       // 148 SMs * 4 CTAs (32KB smem) = one full wave
#define LOOKUP_BLOCKS 444       // 148 SMs * 3 CTAs (64KB smem) = one full wave

// Scratch (allocation-free rule: __device__ globals, zero-initialized at load)
__device__ float g_hist[NUM_NODES * NUM_BINS];
__device__ float g_cdf[NUM_NODES * NUM_BINS];
// 2-byte lookup code per element: bin index if valid, 0xFFFF sentinel if not.
__device__ unsigned short g_code[(size_t)N_PAIRS * K_ELEMS];

extern __shared__ float sh_dyn[];   // role depends on kernel

// ---------------------------------------------------------------------------
// Kernel 1: persistent hist, 4 CTAs/SM (32-reg cap, 32KB smem).
// 16-way replicated smem histogram, conflict-free replica index
// rep = (lane&15 + 8*(lane>>4)) & 15. Total weight is recovered as the scan
// total in cdf_kernel (all residuals in-range), so no wsum machinery.
// Histogram atomic is unconditional with a 1-op clamp. Zeroing fused into
// the reduction. g_hist zero on entry.
// ---------------------------------------------------------------------------
__global__ void __launch_bounds__(512, 4) hist_kernel(
    const float* __restrict__ res, const float* __restrict__ wgt,
    const int* __restrict__ src, const int* __restrict__ dst)
{
    float* tab = sh_dyn;              // NUM_BINS * NREP floats = 32 KB

    const int tid  = threadIdx.x;
    const int lane = tid & 31;
    const int rep  = (lane + ((lane >> 4) << 3)) & 15;   // conflict-free replica

    // one-time zero of the replicated histogram
    float4* shz = (float4*)tab;
    #pragma unroll
    for (int i = 0; i < (NUM_BINS * NREP / 4) / 512; i++)
        shz[tid + i * 512] = make_float4(0.f, 0.f, 0.f, 0.f);
    __syncthreads();

    int lo = (int)(((long long)blockIdx.x       * TOTAL_TASKS) / HIST_BLOCKS);
    int hi = (int)(((long long)(blockIdx.x + 1) * TOTAL_TASKS) / HIST_BLOCKS);

    int t = lo;
    while (t < hi) {
        const int p    = t / TASKS_PER_PAIR;
        const int tend = min(hi, (p + 1) * TASKS_PER_PAIR);

        const float4* r4 = (const float4*)(res + (size_t)p * K_ELEMS);
        const float4* w4 = (const float4*)(wgt + (size_t)p * K_ELEMS);
        ushort4* c4 = (ushort4*)(g_code + (size_t)p * K_ELEMS);

        const int i0 = (t    - p * TASKS_PER_PAIR) * CHUNK_F4;
        const int i1 = (tend - p * TASKS_PER_PAIR) * CHUNK_F4;

        for (int i = i0 + tid; i < i1; i += 512) {
            float4 rv = __ldcs(&r4[i]);   // read-once: stream past L2
            float4 wv = __ldcs(&w4[i]);
            float rr[4] = {rv.x, rv.y, rv.z, rv.w};
            float ww[4] = {wv.x, wv.y, wv.z, wv.w};
            unsigned short cc[4];
            #pragma unroll
            for (int j = 0; j < 4; j++) {
                float x = rr[j] * 512.0f;             // *2^9 exact in fp32
                int b  = min(__float2int_rd(x), NUM_BINS - 1);  // r in [0,1)
                atomicAdd(&tab[b * NREP + rep], ww[j]);         // conflict-free
                int b2 = __float2int_rd(x + 0.5f);    // lookup bin
                bool valid = ((unsigned)b2 < NUM_BINS) && (ww[j] > 0.0f);
                cc[j] = valid ? (unsigned short)b2 : (unsigned short)0xFFFFu;
            }
            c4[i] = make_ushort4(cc[0], cc[1], cc[2], cc[3]);
        }
        __syncthreads();   // all atomics for this pair done

        // ---- reduce 16 replicas -> 1 per bin, zero slots behind the read.
        // r = ((lane>>1)+step)&15: even lanes banks 0..15, odd lanes 16..31,
        // all distinct -> conflict-free LDS/STS.
        const int bin = tid;   // 512 threads == 512 bins
        float h = 0.0f;
        #pragma unroll
        for (int step = 0; step < NREP; step++) {
            int r = ((lane >> 1) + step) & (NREP - 1);
            h += tab[bin * NREP + r];
            tab[bin * NREP + r] = 0.0f;            // ready for next segment
        }

        const int s = src[p];
        const int d = dst[p];
        atomicAdd(&g_hist[s * NUM_BINS + bin], h);
        atomicAdd(&g_hist[d * NUM_BINS + bin], h);
        __syncthreads();           // next segment's atomics start after this

        t = tend;
    }
}

// ---------------------------------------------------------------------------
// Kernel 2: cdf[node,:] = cumsum(hist[node,:]) / (total + 1e-10), where
// total (== tw[node], all residuals in-range) is the scan's own grand total.
// Resets g_hist to zero for the next invocation.
// ---------------------------------------------------------------------------
__global__ __launch_bounds__(512) void cdf_kernel() {
    __shared__ float warp_sums[16];
    __shared__ float inv_total;

    const int node = blockIdx.x;
    const int tid  = threadIdx.x;

    float h = g_hist[node * NUM_BINS + tid];
    g_hist[node * NUM_BINS + tid] = 0.0f;     // reset for next call
    float x = h;

    // intra-warp inclusive scan
    #pragma unroll
    for (int o = 1; o < 32; o <<= 1) {
        float y = __shfl_up_sync(0xffffffffu, x, o);
        if ((tid & 31) >= o) x += y;
    }
    if ((tid & 31) == 31) warp_sums[tid >> 5] = x;
    __syncthreads();

    if (tid < 16) {
        float s = warp_sums[tid];
        #pragma unroll
        for (int o = 1; o < 16; o <<= 1) {
            float y = __shfl_up_sync(0x0000ffffu, s, o);
            if (tid >= o) s += y;
        }
        warp_sums[tid] = s;
        if (tid == 15) inv_total = 1.0f / (s + 1e-10f);   // grand total == tw
    }
    __syncthreads();

    float base = (tid >= 32) ? warp_sums[(tid >> 5) - 1] : 0.0f;
    g_cdf[node * NUM_BINS + tid] = (x + base) * inv_total;
}

// ---------------------------------------------------------------------------
// Kernel 3: persistent lookup (at its HBM write floor — R13 proved the .cs
// streaming stores are worth ~6us; keep them).
// Interleaved float2 cdf table replicated 16x -> conflict-free LDS.64 gather.
// Output layout: out[0 : N*K) = src_cdf, out[N*K : 2*N*K) = dst_cdf.
// ---------------------------------------------------------------------------
__global__ void __launch_bounds__(512, 3) lookup_kernel(
    const int* __restrict__ src, const int* __restrict__ dst,
    float* __restrict__ out)
{
    float2* tab = (float2*)sh_dyn;    // NUM_BINS * LREP float2 = 64 KB

    const int tid    = threadIdx.x;
    const int lane16 = tid & 15;

    int lo = (int)(((long long)blockIdx.x       * TOTAL_TASKS) / LOOKUP_BLOCKS);
    int hi = (int)(((long long)(blockIdx.x + 1) * TOTAL_TASKS) / LOOKUP_BLOCKS);

    int t = lo;
    while (t < hi) {
        const int p    = t / TASKS_PER_PAIR;
        const int tend = min(hi, (p + 1) * TASKS_PER_PAIR);

        __syncthreads();   // previous segment's smem readers are done
        const int s = src[p];
        const int d = dst[p];
        {
            float2 v = make_float2(g_cdf[s * NUM_BINS + tid],
                                   g_cdf[d * NUM_BINS + tid]);
            #pragma unroll
            for (int r = 0; r < LREP; r++)          // stagger: conflict-free STS
                tab[tid * LREP + ((r + tid) & (LREP - 1))] = v;
        }
        __syncthreads();

        const ushort4* c4 = (const ushort4*)(g_code + (size_t)p * K_ELEMS);
        float4* o_s = (float4*)(out + (size_t)p * K_ELEMS);
        float4* o_d = (float4*)(out + (size_t)(N_PAIRS + p) * K_ELEMS);

        const int i0 = (t    - p * TASKS_PER_PAIR) * CHUNK_F4;
        const int i1 = (tend - p * TASKS_PER_PAIR) * CHUNK_F4;

        ushort4 cv = c4[i0 + tid];                  // depth-1 prefetch
        for (int i = i0 + tid; i < i1; i += 512) {
            ushort4 cn;
            if (i + 512 < i1) cn = c4[i + 512];
            unsigned short cc[4] = {cv.x, cv.y, cv.z, cv.w};
            float4 os, od;
            float* pos = (float*)&os;
            float* pod = (float*)&od;
            #pragma unroll
            for (int j = 0; j < 4; j++) {
                unsigned short c = cc[j];
                if (c < NUM_BINS) {
                    float2 v = tab[(int)c * LREP + lane16];   // conflict-free
                    pos[j] = v.x;
                    pod[j] = v.y;
                } else {
                    pos[j] = 2.0f;
                    pod[j] = 2.0f;
                }
            }
            __stcs(&o_s[i], os);   // streaming: never re-read (load-bearing!)
            __stcs(&o_d[i], od);
            cv = cn;
        }

        t = tend;
    }
}

// ---------------------------------------------------------------------------
extern "C" void kernel_launch(void* const* d_in, const int* in_sizes, int n_in,
                              void* d_out, int out_size)
{
    const float* res = (const float*)d_in[0];
    const float* wgt = (const float*)d_in[1];
    const int*   src = (const int*)d_in[2];
    const int*   dst = (const int*)d_in[3];
    float*       out = (float*)d_out;

    const int smem_h = NUM_BINS * NREP * sizeof(float);    // 32 KB
    const int smem_l = NUM_BINS * LREP * sizeof(float2);   // 64 KB
    cudaFuncSetAttribute(hist_kernel,
                         cudaFuncAttributeMaxDynamicSharedMemorySize, smem_h);
    cudaFuncSetAttribute(lookup_kernel,
                         cudaFuncAttributeMaxDynamicSharedMemorySize, smem_l);

    hist_kernel<<<HIST_BLOCKS, 512, smem_h>>>(res, wgt, src, dst);
    cdf_kernel<<<NUM_NODES, 512>>>();
    lookup_kernel<<<LOOKUP_BLOCKS, 512, smem_l>>>(src, dst, out);
}

// round 15
// speedup vs baseline: 1.0968x; 1.0055x over previous
#include <cuda_runtime.h>

#define NUM_BINS  512
#define NUM_NODES 128
#define N_PAIRS   1024
#define K_ELEMS   16384
#define NREP      16            // hist replicas: 32KB/CTA -> 4 CTAs/SM
#define LREP      16            // lookup: 16 float2 replicas -> conflict-free LDS.64

#define TASKS_PER_PAIR 8
#define CHUNK_F4   512          // float4 per task (2048 elems)
#define TOTAL_TASKS (N_PAIRS * TASKS_PER_PAIR)   // 8192
#define HIST_BLOCKS   592       // 148 SMs * 4 CTAs (32KB smem) = one full wave
#define LOOKUP_BLOCKS 444       // 148 SMs * 3 CTAs (64KB smem) = one full wave

// Scratch (allocation-free rule: __device__ globals, zero-initialized at load)
__device__ float g_hist[NUM_NODES * NUM_BINS];
__device__ float g_cdf[NUM_NODES * NUM_BINS];
// 2-byte lookup code per element: bin index if valid, 0xFFFF sentinel if not.
__device__ unsigned short g_code[(size_t)N_PAIRS * K_ELEMS];

extern __shared__ float sh_dyn[];   // role depends on kernel

// ---------------------------------------------------------------------------
// Kernel 1: persistent hist, 4 CTAs/SM (32-reg cap, 32KB smem).
// 16-way replicated smem histogram, conflict-free replica index
// rep = (lane&15 + 8*(lane>>4)) & 15. Total weight recovered as the scan
// total in cdf_kernel. Replica reduction is VECTORIZED: 4xLDS.128+4xSTS.128
// per bin with chunk rotation c=(k+(bin>>1))&3 -> conflict-free, 4x fewer
// smem instructions than the scalar reduce. g_hist zero on entry.
// ---------------------------------------------------------------------------
__global__ void __launch_bounds__(512, 4) hist_kernel(
    const float* __restrict__ res, const float* __restrict__ wgt,
    const int* __restrict__ src, const int* __restrict__ dst)
{
    float* tab = sh_dyn;              // NUM_BINS * NREP floats = 32 KB

    const int tid  = threadIdx.x;
    const int lane = tid & 31;
    const int rep  = (lane + ((lane >> 4) << 3)) & 15;   // conflict-free replica

    // one-time zero of the replicated histogram
    float4* shz = (float4*)tab;
    #pragma unroll
    for (int i = 0; i < (NUM_BINS * NREP / 4) / 512; i++)
        shz[tid + i * 512] = make_float4(0.f, 0.f, 0.f, 0.f);
    __syncthreads();

    int lo = (int)(((long long)blockIdx.x       * TOTAL_TASKS) / HIST_BLOCKS);
    int hi = (int)(((long long)(blockIdx.x + 1) * TOTAL_TASKS) / HIST_BLOCKS);

    int t = lo;
    while (t < hi) {
        const int p    = t / TASKS_PER_PAIR;
        const int tend = min(hi, (p + 1) * TASKS_PER_PAIR);

        const float4* r4 = (const float4*)(res + (size_t)p * K_ELEMS);
        const float4* w4 = (const float4*)(wgt + (size_t)p * K_ELEMS);
        ushort4* c4 = (ushort4*)(g_code + (size_t)p * K_ELEMS);

        const int i0 = (t    - p * TASKS_PER_PAIR) * CHUNK_F4;
        const int i1 = (tend - p * TASKS_PER_PAIR) * CHUNK_F4;

        for (int i = i0 + tid; i < i1; i += 512) {
            float4 rv = __ldcs(&r4[i]);   // read-once: stream past L2
            float4 wv = __ldcs(&w4[i]);
            float rr[4] = {rv.x, rv.y, rv.z, rv.w};
            float ww[4] = {wv.x, wv.y, wv.z, wv.w};
            unsigned short cc[4];
            #pragma unroll
            for (int j = 0; j < 4; j++) {
                float x = rr[j] * 512.0f;             // *2^9 exact in fp32
                int b  = min(__float2int_rd(x), NUM_BINS - 1);  // r in [0,1)
                atomicAdd(&tab[b * NREP + rep], ww[j]);         // conflict-free
                int b2 = __float2int_rd(x + 0.5f);    // lookup bin
                bool valid = ((unsigned)b2 < NUM_BINS) && (ww[j] > 0.0f);
                cc[j] = valid ? (unsigned short)b2 : (unsigned short)0xFFFFu;
            }
            c4[i] = make_ushort4(cc[0], cc[1], cc[2], cc[3]);
        }
        __syncthreads();   // all atomics for this pair done

        // ---- vectorized reduce: 16 replicas -> 1 per bin, zero behind read.
        // chunk rotation c=(k+(bin>>1))&3: within each 8-thread LDS.128
        // phase, even bins take 4B-bank groups {0-3,4-7,8-11,12-15} and odd
        // bins {16-19,...,28-31} -> all distinct, conflict-free (4 wf/instr).
        const int bin = tid;   // 512 threads == 512 bins
        float4* t4 = (float4*)(tab + bin * NREP);
        float h = 0.0f;
        #pragma unroll
        for (int k = 0; k < 4; k++) {
            int c = (k + (bin >> 1)) & 3;
            float4 v = t4[c];
            h += (v.x + v.y) + (v.z + v.w);
            t4[c] = make_float4(0.f, 0.f, 0.f, 0.f);   // ready for next segment
        }

        const int s = src[p];
        const int d = dst[p];
        atomicAdd(&g_hist[s * NUM_BINS + bin], h);
        atomicAdd(&g_hist[d * NUM_BINS + bin], h);
        __syncthreads();           // next segment's atomics start after this

        t = tend;
    }
}

// ---------------------------------------------------------------------------
// Kernel 2: cdf[node,:] = cumsum(hist[node,:]) / (total + 1e-10), where
// total (== tw[node], all residuals in-range) is the scan's own grand total.
// Resets g_hist to zero for the next invocation.
// ---------------------------------------------------------------------------
__global__ __launch_bounds__(512) void cdf_kernel() {
    __shared__ float warp_sums[16];
    __shared__ float inv_total;

    const int node = blockIdx.x;
    const int tid  = threadIdx.x;

    float h = g_hist[node * NUM_BINS + tid];
    g_hist[node * NUM_BINS + tid] = 0.0f;     // reset for next call
    float x = h;

    // intra-warp inclusive scan
    #pragma unroll
    for (int o = 1; o < 32; o <<= 1) {
        float y = __shfl_up_sync(0xffffffffu, x, o);
        if ((tid & 31) >= o) x += y;
    }
    if ((tid & 31) == 31) warp_sums[tid >> 5] = x;
    __syncthreads();

    if (tid < 16) {
        float s = warp_sums[tid];
        #pragma unroll
        for (int o = 1; o < 16; o <<= 1) {
            float y = __shfl_up_sync(0x0000ffffu, s, o);
            if (tid >= o) s += y;
        }
        warp_sums[tid] = s;
        if (tid == 15) inv_total = 1.0f / (s + 1e-10f);   // grand total == tw
    }
    __syncthreads();

    float base = (tid >= 32) ? warp_sums[(tid >> 5) - 1] : 0.0f;
    g_cdf[node * NUM_BINS + tid] = (x + base) * inv_total;
}

// ---------------------------------------------------------------------------
// Kernel 3: persistent lookup (at its HBM write floor — R13 proved the .cs
// streaming stores are worth ~6us; keep them).
// Interleaved float2 cdf table replicated 16x -> conflict-free LDS.64 gather.
// Output layout: out[0 : N*K) = src_cdf, out[N*K : 2*N*K) = dst_cdf.
// ---------------------------------------------------------------------------
__global__ void __launch_bounds__(512, 3) lookup_kernel(
    const int* __restrict__ src, const int* __restrict__ dst,
    float* __restrict__ out)
{
    float2* tab = (float2*)sh_dyn;    // NUM_BINS * LREP float2 = 64 KB

    const int tid    = threadIdx.x;
    const int lane16 = tid & 15;

    int lo = (int)(((long long)blockIdx.x       * TOTAL_TASKS) / LOOKUP_BLOCKS);
    int hi = (int)(((long long)(blockIdx.x + 1) * TOTAL_TASKS) / LOOKUP_BLOCKS);

    int t = lo;
    while (t < hi) {
        const int p    = t / TASKS_PER_PAIR;
        const int tend = min(hi, (p + 1) * TASKS_PER_PAIR);

        __syncthreads();   // previous segment's smem readers are done
        const int s = src[p];
        const int d = dst[p];
        {
            float2 v = make_float2(g_cdf[s * NUM_BINS + tid],
                                   g_cdf[d * NUM_BINS + tid]);
            #pragma unroll
            for (int r = 0; r < LREP; r++)          // stagger: conflict-free STS
                tab[tid * LREP + ((r + tid) & (LREP - 1))] = v;
        }
        __syncthreads();

        const ushort4* c4 = (const ushort4*)(g_code + (size_t)p * K_ELEMS);
        float4* o_s = (float4*)(out + (size_t)p * K_ELEMS);
        float4* o_d = (float4*)(out + (size_t)(N_PAIRS + p) * K_ELEMS);

        const int i0 = (t    - p * TASKS_PER_PAIR) * CHUNK_F4;
        const int i1 = (tend - p * TASKS_PER_PAIR) * CHUNK_F4;

        ushort4 cv = c4[i0 + tid];                  // depth-1 prefetch
        for (int i = i0 + tid; i < i1; i += 512) {
            ushort4 cn;
            if (i + 512 < i1) cn = c4[i + 512];
            unsigned short cc[4] = {cv.x, cv.y, cv.z, cv.w};
            float4 os, od;
            float* pos = (float*)&os;
            float* pod = (float*)&od;
            #pragma unroll
            for (int j = 0; j < 4; j++) {
                unsigned short c = cc[j];
                if (c < NUM_BINS) {
                    float2 v = tab[(int)c * LREP + lane16];   // conflict-free
                    pos[j] = v.x;
                    pod[j] = v.y;
                } else {
                    pos[j] = 2.0f;
                    pod[j] = 2.0f;
                }
            }
            __stcs(&o_s[i], os);   // streaming: never re-read (load-bearing!)
            __stcs(&o_d[i], od);
            cv = cn;
        }

        t = tend;
    }
}

// ---------------------------------------------------------------------------
extern "C" void kernel_launch(void* const* d_in, const int* in_sizes, int n_in,
                              void* d_out, int out_size)
{
    const float* res = (const float*)d_in[0];
    const float* wgt = (const float*)d_in[1];
    const int*   src = (const int*)d_in[2];
    const int*   dst = (const int*)d_in[3];
    float*       out = (float*)d_out;

    const int smem_h = NUM_BINS * NREP * sizeof(float);    // 32 KB
    const int smem_l = NUM_BINS * LREP * sizeof(float2);   // 64 KB
    cudaFuncSetAttribute(hist_kernel,
                         cudaFuncAttributeMaxDynamicSharedMemorySize, smem_h);
    cudaFuncSetAttribute(lookup_kernel,
                         cudaFuncAttributeMaxDynamicSharedMemorySize, smem_l);

    hist_kernel<<<HIST_BLOCKS, 512, smem_h>>>(res, wgt, src, dst);
    cdf_kernel<<<NUM_NODES, 512>>>();
    lookup_kernel<<<LOOKUP_BLOCKS, 512, smem_l>>>(src, dst, out);
}

// round 16
// speedup vs baseline: 1.1029x; 1.0056x over previous
#include <cuda_runtime.h>

#define NUM_BINS  512
#define NUM_NODES 128
#define N_PAIRS   1024
#define K_ELEMS   16384
#define NREP      16            // hist replicas: 32KB/CTA -> 4 CTAs/SM
#define LREP      16            // lookup: 16 float2 replicas -> conflict-free LDS.64

#define TASKS_PER_PAIR 8
#define CHUNK_F4   512          // float4 per task (2048 elems)
#define TOTAL_TASKS (N_PAIRS * TASKS_PER_PAIR)   // 8192
#define HIST_BLOCKS   592       // 148 SMs * 4 CTAs (32KB smem) = one full wave
#define LOOKUP_BLOCKS 444       // 148 SMs * 3 CTAs (64KB smem) = one full wave

// Scratch (allocation-free rule: __device__ globals, zero-initialized at load)
__device__ float g_hist[NUM_NODES * NUM_BINS];
__device__ float g_cdf[NUM_NODES * NUM_BINS];
// 2-byte lookup code per element: bin index if valid, 0xFFFF sentinel if not.
__device__ unsigned short g_code[(size_t)N_PAIRS * K_ELEMS];

extern __shared__ float sh_dyn[];   // role depends on kernel

// ---------------------------------------------------------------------------
// Kernel 1: persistent hist, 4 CTAs/SM (32-reg cap, 32KB smem).
// 16-way replicated smem histogram, conflict-free replica index
// rep = (lane&15 + 8*(lane>>4)) & 15. Total weight recovered as the scan
// total in cdf_kernel. Vectorized replica reduction (4xLDS.128+4xSTS.128,
// chunk rotation -> conflict-free). Unchanged from R15 — near floor.
// ---------------------------------------------------------------------------
__global__ void __launch_bounds__(512, 4) hist_kernel(
    const float* __restrict__ res, const float* __restrict__ wgt,
    const int* __restrict__ src, const int* __restrict__ dst)
{
    float* tab = sh_dyn;              // NUM_BINS * NREP floats = 32 KB

    const int tid  = threadIdx.x;
    const int lane = tid & 31;
    const int rep  = (lane + ((lane >> 4) << 3)) & 15;   // conflict-free replica

    // one-time zero of the replicated histogram
    float4* shz = (float4*)tab;
    #pragma unroll
    for (int i = 0; i < (NUM_BINS * NREP / 4) / 512; i++)
        shz[tid + i * 512] = make_float4(0.f, 0.f, 0.f, 0.f);
    __syncthreads();

    int lo = (int)(((long long)blockIdx.x       * TOTAL_TASKS) / HIST_BLOCKS);
    int hi = (int)(((long long)(blockIdx.x + 1) * TOTAL_TASKS) / HIST_BLOCKS);

    int t = lo;
    while (t < hi) {
        const int p    = t / TASKS_PER_PAIR;
        const int tend = min(hi, (p + 1) * TASKS_PER_PAIR);

        const float4* r4 = (const float4*)(res + (size_t)p * K_ELEMS);
        const float4* w4 = (const float4*)(wgt + (size_t)p * K_ELEMS);
        ushort4* c4 = (ushort4*)(g_code + (size_t)p * K_ELEMS);

        const int i0 = (t    - p * TASKS_PER_PAIR) * CHUNK_F4;
        const int i1 = (tend - p * TASKS_PER_PAIR) * CHUNK_F4;

        for (int i = i0 + tid; i < i1; i += 512) {
            float4 rv = __ldcs(&r4[i]);   // read-once: stream past L2
            float4 wv = __ldcs(&w4[i]);
            float rr[4] = {rv.x, rv.y, rv.z, rv.w};
            float ww[4] = {wv.x, wv.y, wv.z, wv.w};
            unsigned short cc[4];
            #pragma unroll
            for (int j = 0; j < 4; j++) {
                float x = rr[j] * 512.0f;             // *2^9 exact in fp32
                int b  = min(__float2int_rd(x), NUM_BINS - 1);  // r in [0,1)
                atomicAdd(&tab[b * NREP + rep], ww[j]);         // conflict-free
                int b2 = __float2int_rd(x + 0.5f);    // lookup bin
                bool valid = ((unsigned)b2 < NUM_BINS) && (ww[j] > 0.0f);
                cc[j] = valid ? (unsigned short)b2 : (unsigned short)0xFFFFu;
            }
            c4[i] = make_ushort4(cc[0], cc[1], cc[2], cc[3]);
        }
        __syncthreads();   // all atomics for this pair done

        // ---- vectorized reduce: 16 replicas -> 1 per bin, zero behind read.
        const int bin = tid;   // 512 threads == 512 bins
        float4* t4 = (float4*)(tab + bin * NREP);
        float h = 0.0f;
        #pragma unroll
        for (int k = 0; k < 4; k++) {
            int c = (k + (bin >> 1)) & 3;
            float4 v = t4[c];
            h += (v.x + v.y) + (v.z + v.w);
            t4[c] = make_float4(0.f, 0.f, 0.f, 0.f);   // ready for next segment
        }

        const int s = src[p];
        const int d = dst[p];
        atomicAdd(&g_hist[s * NUM_BINS + bin], h);
        atomicAdd(&g_hist[d * NUM_BINS + bin], h);
        __syncthreads();           // next segment's atomics start after this

        t = tend;
    }
}

// ---------------------------------------------------------------------------
// Kernel 2: cdf[node,:] = cumsum(hist[node,:]) / (total + 1e-10); the grand
// total equals tw[node]. Resets g_hist for the next invocation.
// ---------------------------------------------------------------------------
__global__ __launch_bounds__(512) void cdf_kernel() {
    __shared__ float warp_sums[16];
    __shared__ float inv_total;

    const int node = blockIdx.x;
    const int tid  = threadIdx.x;

    float h = g_hist[node * NUM_BINS + tid];
    g_hist[node * NUM_BINS + tid] = 0.0f;     // reset for next call
    float x = h;

    #pragma unroll
    for (int o = 1; o < 32; o <<= 1) {
        float y = __shfl_up_sync(0xffffffffu, x, o);
        if ((tid & 31) >= o) x += y;
    }
    if ((tid & 31) == 31) warp_sums[tid >> 5] = x;
    __syncthreads();

    if (tid < 16) {
        float s = warp_sums[tid];
        #pragma unroll
        for (int o = 1; o < 16; o <<= 1) {
            float y = __shfl_up_sync(0x0000ffffu, s, o);
            if (tid >= o) s += y;
        }
        warp_sums[tid] = s;
        if (tid == 15) inv_total = 1.0f / (s + 1e-10f);   // grand total == tw
    }
    __syncthreads();

    float base = (tid >= 32) ? warp_sums[(tid >> 5) - 1] : 0.0f;
    g_cdf[node * NUM_BINS + tid] = (x + base) * inv_total;
}

// ---------------------------------------------------------------------------
// Kernel 3: persistent lookup. CLEAN store-ILP test: 2 code vectors + 4
// streaming stores in flight per iteration, __stcs RETAINED (R13 proved it
// load-bearing), LREP=16 / 3 CTAs/SM (42-reg cap — room for the extra live
// state, unlike R13's 32-reg cap which likely spilled).
// Output layout: out[0 : N*K) = src_cdf, out[N*K : 2*N*K) = dst_cdf.
// ---------------------------------------------------------------------------
__device__ __forceinline__ void lk_one(
    ushort4 cv, const float2* tab, int lane16, float4& os, float4& od)
{
    unsigned short cc[4] = {cv.x, cv.y, cv.z, cv.w};
    float* pos = (float*)&os;
    float* pod = (float*)&od;
    #pragma unroll
    for (int j = 0; j < 4; j++) {
        unsigned short c = cc[j];
        if (c < NUM_BINS) {
            float2 v = tab[(int)c * LREP + lane16];   // conflict-free LDS.64
            pos[j] = v.x;
            pod[j] = v.y;
        } else {
            pos[j] = 2.0f;
            pod[j] = 2.0f;
        }
    }
}

__global__ void __launch_bounds__(512, 3) lookup_kernel(
    const int* __restrict__ src, const int* __restrict__ dst,
    float* __restrict__ out)
{
    float2* tab = (float2*)sh_dyn;    // NUM_BINS * LREP float2 = 64 KB

    const int tid    = threadIdx.x;
    const int lane16 = tid & 15;

    int lo = (int)(((long long)blockIdx.x       * TOTAL_TASKS) / LOOKUP_BLOCKS);
    int hi = (int)(((long long)(blockIdx.x + 1) * TOTAL_TASKS) / LOOKUP_BLOCKS);

    int t = lo;
    while (t < hi) {
        const int p    = t / TASKS_PER_PAIR;
        const int tend = min(hi, (p + 1) * TASKS_PER_PAIR);

        __syncthreads();   // previous segment's smem readers are done
        const int s = src[p];
        const int d = dst[p];
        {
            float2 v = make_float2(g_cdf[s * NUM_BINS + tid],
                                   g_cdf[d * NUM_BINS + tid]);
            #pragma unroll
            for (int r = 0; r < LREP; r++)          // stagger: conflict-free STS
                tab[tid * LREP + ((r + tid) & (LREP - 1))] = v;
        }
        __syncthreads();

        const ushort4* c4 = (const ushort4*)(g_code + (size_t)p * K_ELEMS);
        float4* o_s = (float4*)(out + (size_t)p * K_ELEMS);
        float4* o_d = (float4*)(out + (size_t)(N_PAIRS + p) * K_ELEMS);

        const int i0 = (t    - p * TASKS_PER_PAIR) * CHUNK_F4;
        const int i1 = (tend - p * TASKS_PER_PAIR) * CHUNK_F4;

        // two code vectors + four .cs stores in flight per iteration
        int i = i0 + tid;
        for (; i + 512 < i1; i += 1024) {
            ushort4 cv0 = c4[i];
            ushort4 cv1 = c4[i + 512];
            float4 os0, od0, os1, od1;
            lk_one(cv0, tab, lane16, os0, od0);
            lk_one(cv1, tab, lane16, os1, od1);
            __stcs(&o_s[i],       os0);
            __stcs(&o_d[i],       od0);
            __stcs(&o_s[i + 512], os1);
            __stcs(&o_d[i + 512], od1);
        }
        if (i < i1) {
            ushort4 cv = c4[i];
            float4 os, od;
            lk_one(cv, tab, lane16, os, od);
            __stcs(&o_s[i], os);
            __stcs(&o_d[i], od);
        }

        t = tend;
    }
}

// ---------------------------------------------------------------------------
extern "C" void kernel_launch(void* const* d_in, const int* in_sizes, int n_in,
                              void* d_out, int out_size)
{
    const float* res = (const float*)d_in[0];
    const float* wgt = (const float*)d_in[1];
    const int*   src = (const int*)d_in[2];
    const int*   dst = (const int*)d_in[3];
    float*       out = (float*)d_out;

    const int smem_h = NUM_BINS * NREP * sizeof(float);    // 32 KB
    const int smem_l = NUM_BINS * LREP * sizeof(float2);   // 64 KB
    cudaFuncSetAttribute(hist_kernel,
                         cudaFuncAttributeMaxDynamicSharedMemorySize, smem_h);
    cudaFuncSetAttribute(lookup_kernel,
                         cudaFuncAttributeMaxDynamicSharedMemorySize, smem_l);

    hist_kernel<<<HIST_BLOCKS, 512, smem_h>>>(res, wgt, src, dst);
    cdf_kernel<<<NUM_NODES, 512>>>();
    lookup_kernel<<<LOOKUP_BLOCKS, 512, smem_l>>>(src, dst, out);
}